// round 7
// baseline (speedup 1.0000x reference)
#include <cuda_runtime.h>
#include <cuda_bf16.h>
#include <mma.h>
#include <math.h>

using namespace nvcuda;

// ---------------------------------------------------------------------------
// Problem constants
// ---------------------------------------------------------------------------
#define PB     2
#define PT     2048
#define PC     2048
#define PH     32
#define PKVH   8
#define PHD    64
#define PKV    (PKVH * PHD)      // 512
#define PKV2   (2 * PKV)         // 1024 (k||v fused)
#define PM     (PB * PT)         // 4096

// ---------------------------------------------------------------------------
// Device scratch (no cudaMalloc allowed)
// ---------------------------------------------------------------------------
__device__ float g_q[PM * PC];        // 32 MB
__device__ float g_kv[PM * PKV2];     // 16 MB  (row: k[512] || v[512])
__device__ float g_wkv[PC * PKV2];    //  8 MB  (wk || wv, row-major)
__device__ float g_attn[PM * PC];     // 32 MB
__device__ float g_cos[PT * 32];
__device__ float g_sin[PT * 32];

// ---------------------------------------------------------------------------
// cp.async helpers
// ---------------------------------------------------------------------------
__device__ __forceinline__ void cp_async16(void* s, const void* g) {
    unsigned sa = (unsigned)__cvta_generic_to_shared(s);
    asm volatile("cp.async.cg.shared.global [%0], [%1], 16;" :: "r"(sa), "l"(g));
}
__device__ __forceinline__ void cp_commit() {
    asm volatile("cp.async.commit_group;");
}
template<int N> __device__ __forceinline__ void cp_wait() {
    asm volatile("cp.async.wait_group %0;" :: "n"(N));
}

// ---------------------------------------------------------------------------
// TF32 GEMM: C[M,N] = A[M,K] @ B[K,N], row-major fp32.
// Block 128x128, BK=32, 3-stage cp.async, 256 thr = 8 warps (4x2),
// warp tile 32x64 (FM=2, FN=4).  2 CTAs/SM (regs<=128, smem 106KB/CTA).
// ---------------------------------------------------------------------------
#define GBM 128
#define GBN 128
#define GBK 32
#define GAP 36     // A smem pitch
#define GBP 132    // B smem pitch
#define GST 3      // stages

__global__ __launch_bounds__(256, 2)
void gemm_kernel(const float* __restrict__ A, const float* __restrict__ B,
                 float* __restrict__ C, int M, int N, int K) {
    extern __shared__ float smem[];
    float* As = smem;                       // GST * 128 * 36
    float* Bs = smem + GST * GBM * GAP;     // GST * 32 * 132

    const int tid  = threadIdx.x;
    const int warp = tid >> 5;
    const int wm   = warp >> 1;             // 0..3
    const int wn   = warp & 1;              // 0..1
    const int bm   = blockIdx.y * GBM;
    const int bn   = blockIdx.x * GBN;

    wmma::fragment<wmma::accumulator, 16, 16, 8, float> acc[2][4];
    #pragma unroll
    for (int i = 0; i < 2; i++)
        #pragma unroll
        for (int j = 0; j < 4; j++)
            wmma::fill_fragment(acc[i][j], 0.0f);

    auto load_stage = [&](int s, int k0) {
        #pragma unroll
        for (int i = 0; i < 4; i++) {                       // A: 1024 float4
            int idx = tid + i * 256;
            int r = idx >> 3, c = (idx & 7) * 4;
            cp_async16(&As[(s * GBM + r) * GAP + c],
                       &A[(size_t)(bm + r) * K + k0 + c]);
        }
        #pragma unroll
        for (int i = 0; i < 4; i++) {                       // B: 1024 float4
            int idx = tid + i * 256;
            int r = idx >> 5, c = (idx & 31) * 4;
            cp_async16(&Bs[(s * GBK + r) * GBP + c],
                       &B[(size_t)(k0 + r) * N + bn + c]);
        }
    };

    const int KT = K / GBK;
    load_stage(0, 0);
    cp_commit();
    if (KT > 1) { load_stage(1, GBK); cp_commit(); }

    for (int kt = 0; kt < KT; kt++) {
        if (kt + 2 < KT) {
            load_stage((kt + 2) % GST, (kt + 2) * GBK);
            cp_commit();
            cp_wait<2>();
        } else if (kt + 1 < KT) {
            cp_wait<1>();
        } else {
            cp_wait<0>();
        }
        __syncthreads();

        const float* as = &As[(kt % GST) * GBM * GAP];
        const float* bs = &Bs[(kt % GST) * GBK * GBP];

        #pragma unroll
        for (int kk = 0; kk < GBK; kk += 8) {
            wmma::fragment<wmma::matrix_a, 16, 16, 8, wmma::precision::tf32, wmma::row_major> af[2];
            #pragma unroll
            for (int i = 0; i < 2; i++) {
                wmma::load_matrix_sync(af[i], &as[(wm * 32 + i * 16) * GAP + kk], GAP);
                #pragma unroll
                for (int e = 0; e < af[i].num_elements; e++)
                    af[i].x[e] = wmma::__float_to_tf32(af[i].x[e]);
            }
            #pragma unroll
            for (int j = 0; j < 4; j++) {
                wmma::fragment<wmma::matrix_b, 16, 16, 8, wmma::precision::tf32, wmma::row_major> bf;
                wmma::load_matrix_sync(bf, &bs[kk * GBP + wn * 64 + j * 16], GBP);
                #pragma unroll
                for (int e = 0; e < bf.num_elements; e++)
                    bf.x[e] = wmma::__float_to_tf32(bf.x[e]);
                #pragma unroll
                for (int i = 0; i < 2; i++)
                    wmma::mma_sync(acc[i][j], af[i], bf, acc[i][j]);
            }
        }
        __syncthreads();   // protects stage buffer reuse (kt+1 writes (kt+3)%3 == kt%3)
    }

    #pragma unroll
    for (int i = 0; i < 2; i++)
        #pragma unroll
        for (int j = 0; j < 4; j++)
            wmma::store_matrix_sync(
                &C[(size_t)(bm + wm * 32 + i * 16) * N + bn + wn * 64 + j * 16],
                acc[i][j], N, wmma::mem_row_major);
}

#define GEMM_SMEM ((GST * GBM * GAP + GST * GBK * GBP) * sizeof(float))  // 105984

// ---------------------------------------------------------------------------
// Concatenate wk || wv into g_wkv  [2048 rows x 1024 cols]
// ---------------------------------------------------------------------------
__global__ void concat_wkv_kernel(const float* __restrict__ wk,
                                  const float* __restrict__ wv,
                                  float* __restrict__ wkv) {
    int idx = blockIdx.x * blockDim.x + threadIdx.x;   // float4 index
    if (idx >= PC * (PKV2 / 4)) return;
    int r  = idx >> 8;            // 0..2047
    int c4 = idx & 255;           // 0..255
    float4 val = (c4 < 128)
        ? reinterpret_cast<const float4*>(wk)[r * 128 + c4]
        : reinterpret_cast<const float4*>(wv)[r * 128 + (c4 - 128)];
    reinterpret_cast<float4*>(wkv)[idx] = val;
}

// ---------------------------------------------------------------------------
// RoPE tables (double precision, once per launch)
// ---------------------------------------------------------------------------
__global__ void rope_table_kernel() {
    int idx = blockIdx.x * blockDim.x + threadIdx.x;
    if (idx >= PT * 32) return;
    int t = idx >> 5, i = idx & 31;
    double freq = exp(-(double)i * (9.210340371976184 / 32.0)); // ln(10000)/32
    double s, c;
    sincos((double)t * freq, &s, &c);
    g_cos[idx] = (float)c;
    g_sin[idx] = (float)s;
}

// RoPE on q (contiguous [PM, PC])
__global__ void rope_apply_q_kernel(float* __restrict__ buf) {
    int idx = blockIdx.x * blockDim.x + threadIdx.x;   // pair index
    if (idx >= PM * (PC / 2)) return;
    int row = idx >> 10;                 // / 1024 pairs per row
    int p   = idx & 1023;
    int i   = p & 31;
    int t   = row & (PT - 1);
    float c = g_cos[t * 32 + i], s = g_sin[t * 32 + i];
    float2 v = reinterpret_cast<float2*>(buf)[idx];
    float2 r;
    r.x = v.x * c - v.y * s;
    r.y = v.x * s + v.y * c;
    reinterpret_cast<float2*>(buf)[idx] = r;
}

// RoPE on k half of g_kv (rows PM, 8 heads x 64, row pitch 1024)
__global__ void rope_apply_k_kernel(float* __restrict__ buf) {
    int idx = blockIdx.x * blockDim.x + threadIdx.x;   // pair index
    if (idx >= PM * 256) return;
    int row  = idx >> 8;
    int p    = idx & 255;
    int i    = p & 31;
    int head = p >> 5;
    int t    = row & (PT - 1);
    float c = g_cos[t * 32 + i], s = g_sin[t * 32 + i];
    float* base = buf + (size_t)row * PKV2 + head * 64 + 2 * i;
    float2 v = *reinterpret_cast<float2*>(base);
    float2 r;
    r.x = v.x * c - v.y * s;
    r.y = v.x * s + v.y * c;
    *reinterpret_cast<float2*>(base) = r;
}

// ---------------------------------------------------------------------------
// Flash attention (non-causal, GQA rep=4).
// One block = (b, h, 128-query tile). 256 thr = 8 warps, warp w owns rows
// [w*16, w*16+16). KV tiles of 64 from fused g_kv, cp.async double-buffered.
// Q fragments resident in registers for the whole KV loop.
// PV accumulates into Os via accumulator-fragment load (no Ts tile).
// smem floats: Qs 128*72 | Ks 2*64*72 | Vs 2*64*72 | Ss 128*72 | Os 128*72
//              | mrow 128 | lrow 128      = 46,336 fl = 185,344 B
// ---------------------------------------------------------------------------
#define ALD 72

__global__ __launch_bounds__(256, 1)
void attn_kernel(const float* __restrict__ Q, const float* __restrict__ KV,
                 float* __restrict__ Out) {
    extern __shared__ float sm[];
    float* Qs   = sm;                   // 128*72
    float* Ks   = Qs  + 128 * ALD;      // 2 * 64*72
    float* Vs   = Ks  + 2 * 64 * ALD;   // 2 * 64*72
    float* Ss   = Vs  + 2 * 64 * ALD;   // 128*72
    float* Os   = Ss  + 128 * ALD;      // 128*72
    float* mrow = Os  + 128 * ALD;      // 128
    float* lrow = mrow + 128;           // 128

    const int tid  = threadIdx.x;
    const int warp = tid >> 5;
    const int qb = blockIdx.x, h = blockIdx.y, b = blockIdx.z;
    const int kh = h >> 2;                        // rep = 4
    const float scale = 0.125f;                   // 1/sqrt(64)

    const float* qg = Q  + ((size_t)(b * PT + qb * 128)) * PC + h * 64;
    const float* kg = KV + ((size_t)b * PT) * PKV2 + kh * 64;        // k half
    const float* vg = kg + PKV;                                      // v half

    // Load Q tile + KV tile 0 (group 0), KV tile 1 (group 1).
    #pragma unroll
    for (int i = 0; i < 8; i++) {
        int idx = tid + i * 256;                  // 2048 float4 (128 x 16)
        int r = idx >> 4, c = (idx & 15) * 4;
        cp_async16(&Qs[r * ALD + c], &qg[(size_t)r * PC + c]);
    }
    auto load_kv = [&](int s, int s0) {
        #pragma unroll
        for (int i = 0; i < 4; i++) {             // 1024 float4 per tensor
            int idx = tid + i * 256;
            int r = idx >> 4, c = (idx & 15) * 4;
            size_t g = (size_t)(s0 + r) * PKV2 + c;
            cp_async16(&Ks[(s * 64 + r) * ALD + c], &kg[g]);
            cp_async16(&Vs[(s * 64 + r) * ALD + c], &vg[g]);
        }
    };
    load_kv(0, 0);
    cp_commit();                 // group 0 : Q + KV0
    load_kv(1, 64);
    cp_commit();                 // group 1 : KV1

    // Zero Os, init m/l.
    #pragma unroll
    for (int i = 0; i < 9; i++)                    // 128*72/4 = 2304 float4
        reinterpret_cast<float4*>(Os)[tid + i * 256] = make_float4(0.f, 0.f, 0.f, 0.f);
    if (tid < 128) { mrow[tid] = -1e30f; lrow[tid] = 0.f; }

    cp_wait<1>();                // Q + KV0 landed
    __syncthreads();

    // Hoist Q fragments for this warp's 16 rows (resident across all KV tiles).
    wmma::fragment<wmma::matrix_a, 16, 16, 8, wmma::precision::tf32, wmma::row_major> qf[8];
    #pragma unroll
    for (int kk = 0; kk < 8; kk++) {
        wmma::load_matrix_sync(qf[kk], &Qs[warp * 16 * ALD + kk * 8], ALD);
        #pragma unroll
        for (int e = 0; e < qf[kk].num_elements; e++)
            qf[kk].x[e] = wmma::__float_to_tf32(qf[kk].x[e]);
    }

    const int NT = PT / 64;      // 32 KV tiles
    for (int it = 0; it < NT; it++) {
        if (it >= 1 && it + 1 < NT) {
            load_kv((it + 1) & 1, (it + 1) * 64);
            cp_commit();
            cp_wait<1>();
        } else {
            cp_wait<0>();
        }
        __syncthreads();                                   // syncA

        const float* ks = &Ks[(it & 1) * 64 * ALD];
        const float* vs = &Vs[(it & 1) * 64 * ALD];

        // S = Q @ K^T  (warp: 16 rows x 64 keys)
        {
            wmma::fragment<wmma::accumulator, 16, 16, 8, float> sacc[4];
            #pragma unroll
            for (int j = 0; j < 4; j++) wmma::fill_fragment(sacc[j], 0.f);
            #pragma unroll
            for (int kk = 0; kk < 8; kk++) {
                #pragma unroll
                for (int j = 0; j < 4; j++) {
                    wmma::fragment<wmma::matrix_b, 16, 16, 8, wmma::precision::tf32, wmma::col_major> bf;
                    wmma::load_matrix_sync(bf, &ks[j * 16 * ALD + kk * 8], ALD);
                    #pragma unroll
                    for (int e = 0; e < bf.num_elements; e++)
                        bf.x[e] = wmma::__float_to_tf32(bf.x[e]);
                    wmma::mma_sync(sacc[j], qf[kk], bf, sacc[j]);
                }
            }
            #pragma unroll
            for (int j = 0; j < 4; j++)
                wmma::store_matrix_sync(&Ss[warp * 16 * ALD + j * 16], sacc[j],
                                        ALD, wmma::mem_row_major);
        }
        __syncthreads();                                   // syncB

        // Online softmax + O rescale: 2 threads per row, 32 cols each.
        {
            int row  = tid >> 1;
            int half = tid & 1;
            float* srow = &Ss[row * ALD + half * 32];
            float m_old = mrow[row];
            float rm = -1e30f;
            #pragma unroll
            for (int c = 0; c < 32; c++) rm = fmaxf(rm, srow[c] * scale);
            rm = fmaxf(rm, __shfl_xor_sync(0xFFFFFFFFu, rm, 1));
            rm = fmaxf(rm, m_old);
            float sum = 0.f;
            #pragma unroll
            for (int c = 0; c < 32; c++) {
                float p = __expf(srow[c] * scale - rm);
                srow[c] = p;
                sum += p;
            }
            sum += __shfl_xor_sync(0xFFFFFFFFu, sum, 1);
            float corr = __expf(m_old - rm);
            float* orow = &Os[row * ALD + half * 32];
            #pragma unroll
            for (int c = 0; c < 32; c++) orow[c] *= corr;
            if (half == 0) {
                mrow[row] = rm;
                lrow[row] = lrow[row] * corr + sum;
            }
        }
        __syncthreads();                                   // syncC

        // O += P @ V  (accumulate directly into Os)
        {
            wmma::fragment<wmma::accumulator, 16, 16, 8, float> oacc[4];
            #pragma unroll
            for (int j = 0; j < 4; j++)
                wmma::load_matrix_sync(oacc[j], &Os[warp * 16 * ALD + j * 16],
                                       ALD, wmma::mem_row_major);
            #pragma unroll
            for (int kk = 0; kk < 8; kk++) {
                wmma::fragment<wmma::matrix_a, 16, 16, 8, wmma::precision::tf32, wmma::row_major> af;
                wmma::load_matrix_sync(af, &Ss[warp * 16 * ALD + kk * 8], ALD);
                #pragma unroll
                for (int e = 0; e < af.num_elements; e++)
                    af.x[e] = wmma::__float_to_tf32(af.x[e]);
                #pragma unroll
                for (int j = 0; j < 4; j++) {
                    wmma::fragment<wmma::matrix_b, 16, 16, 8, wmma::precision::tf32, wmma::row_major> bf;
                    wmma::load_matrix_sync(bf, &vs[kk * 8 * ALD + j * 16], ALD);
                    #pragma unroll
                    for (int e = 0; e < bf.num_elements; e++)
                        bf.x[e] = wmma::__float_to_tf32(bf.x[e]);
                    wmma::mma_sync(oacc[j], af, bf, oacc[j]);
                }
            }
            #pragma unroll
            for (int j = 0; j < 4; j++)
                wmma::store_matrix_sync(&Os[warp * 16 * ALD + j * 16], oacc[j],
                                        ALD, wmma::mem_row_major);
        }
        __syncthreads();                                   // syncD
    }

    // Write O / l
    float* og = Out + ((size_t)(b * PT + qb * 128)) * PC + h * 64;
    #pragma unroll
    for (int i = 0; i < 32; i++) {
        int idx = tid + i * 256;                  // 0..8191
        int r = idx >> 6, c = idx & 63;
        og[(size_t)r * PC + c] = Os[r * ALD + c] / lrow[r];
    }
}

#define ATTN_SMEM_BYTES ((5 * 128 * ALD + 2 * 128) * sizeof(float))  // 185344

// ---------------------------------------------------------------------------
// Launch
// ---------------------------------------------------------------------------
extern "C" void kernel_launch(void* const* d_in, const int* in_sizes, int n_in,
                              void* d_out, int out_size) {
    const float* x  = (const float*)d_in[0];
    const float* wq = (const float*)d_in[1];
    const float* wk = (const float*)d_in[2];
    const float* wv = (const float*)d_in[3];
    const float* wo = (const float*)d_in[4];
    float* out = (float*)d_out;

    float *q, *kv, *wkv, *a;
    cudaGetSymbolAddress((void**)&q,   g_q);
    cudaGetSymbolAddress((void**)&kv,  g_kv);
    cudaGetSymbolAddress((void**)&wkv, g_wkv);
    cudaGetSymbolAddress((void**)&a,   g_attn);

    cudaFuncSetAttribute(gemm_kernel,
                         cudaFuncAttributeMaxDynamicSharedMemorySize, (int)GEMM_SMEM);
    cudaFuncSetAttribute(attn_kernel,
                         cudaFuncAttributeMaxDynamicSharedMemorySize, (int)ATTN_SMEM_BYTES);

    // Tables + fused KV weight (cheap, deterministic)
    rope_table_kernel<<<(PT * 32 + 255) / 256, 256>>>();
    concat_wkv_kernel<<<(PC * (PKV2 / 4) + 255) / 256, 256>>>(wk, wv, wkv);

    // Projections
    gemm_kernel<<<dim3(PC / GBN,   PM / GBM), 256, GEMM_SMEM>>>(x, wq,  q,  PM, PC,   PC);
    gemm_kernel<<<dim3(PKV2 / GBN, PM / GBM), 256, GEMM_SMEM>>>(x, wkv, kv, PM, PKV2, PC);

    // RoPE on q and k
    rope_apply_q_kernel<<<(PM * (PC / 2) + 255) / 256, 256>>>(q);
    rope_apply_k_kernel<<<(PM * 256 + 255) / 256, 256>>>(kv);

    // Attention
    attn_kernel<<<dim3(PT / 128, PH, PB), 256, ATTN_SMEM_BYTES>>>(q, kv, a);

    // Output projection
    gemm_kernel<<<dim3(PC / GBN, PM / GBM), 256, GEMM_SMEM>>>(a, wo, out, PM, PC, PC);
}

// round 9
// speedup vs baseline: 1.4485x; 1.4485x over previous
#include <cuda_runtime.h>
#include <cuda_bf16.h>
#include <mma.h>
#include <math.h>

using namespace nvcuda;

// ---------------------------------------------------------------------------
// Problem constants
// ---------------------------------------------------------------------------
#define PB     2
#define PT     2048
#define PC     2048
#define PH     32
#define PKVH   8
#define PHD    64
#define PKV    (PKVH * PHD)      // 512
#define PKV2   (2 * PKV)         // 1024 (k||v fused)
#define PM     (PB * PT)         // 4096

// ---------------------------------------------------------------------------
// Device scratch (no cudaMalloc allowed)
// ---------------------------------------------------------------------------
__device__ float g_q[PM * PC];        // 32 MB
__device__ float g_kv[PM * PKV2];     // 16 MB  (row: k[512] || v[512])
__device__ float g_wkv[PC * PKV2];    //  8 MB  (wk || wv, row-major)
__device__ float g_attn[PM * PC];     // 32 MB
__device__ float g_cos[PT * 32];
__device__ float g_sin[PT * 32];

// ---------------------------------------------------------------------------
// cp.async helpers
// ---------------------------------------------------------------------------
__device__ __forceinline__ void cp_async16(void* s, const void* g) {
    unsigned sa = (unsigned)__cvta_generic_to_shared(s);
    asm volatile("cp.async.cg.shared.global [%0], [%1], 16;" :: "r"(sa), "l"(g));
}
__device__ __forceinline__ void cp_commit() {
    asm volatile("cp.async.commit_group;");
}
template<int N> __device__ __forceinline__ void cp_wait() {
    asm volatile("cp.async.wait_group %0;" :: "n"(N));
}

// ---------------------------------------------------------------------------
// TF32 GEMM: C[M,N] = A[M,K] @ B[K,N], row-major fp32.
// Block 128x128, BK=32, 3-stage cp.async. 512 threads = 16 warps (4x4),
// warp tile 32x32 (acc = 32 regs/thread -> no spill risk at the 128-reg
// hardware ceiling for 512-thread CTAs). 16 warps/SM = 25% occ, 1 CTA/SM.
// ---------------------------------------------------------------------------
#define GBM 128
#define GBN 128
#define GBK 32
#define GAP 36     // A smem pitch
#define GBP 132    // B smem pitch
#define GST 3      // stages

__global__ __launch_bounds__(512)
void gemm_kernel(const float* __restrict__ A, const float* __restrict__ B,
                 float* __restrict__ C, int M, int N, int K) {
    extern __shared__ float smem[];
    float* As = smem;                       // GST * 128 * 36
    float* Bs = smem + GST * GBM * GAP;     // GST * 32 * 132

    const int tid  = threadIdx.x;
    const int warp = tid >> 5;
    const int wm   = warp >> 2;             // 0..3 (M dir)
    const int wn   = warp & 3;              // 0..3 (N dir)
    const int bm   = blockIdx.y * GBM;
    const int bn   = blockIdx.x * GBN;

    wmma::fragment<wmma::accumulator, 16, 16, 8, float> acc[2][2];
    #pragma unroll
    for (int i = 0; i < 2; i++)
        #pragma unroll
        for (int j = 0; j < 2; j++)
            wmma::fill_fragment(acc[i][j], 0.0f);

    auto load_stage = [&](int s, int k0) {
        #pragma unroll
        for (int i = 0; i < 2; i++) {                       // A: 1024 float4
            int idx = tid + i * 512;
            int r = idx >> 3, c = (idx & 7) * 4;
            cp_async16(&As[(s * GBM + r) * GAP + c],
                       &A[(size_t)(bm + r) * K + k0 + c]);
        }
        #pragma unroll
        for (int i = 0; i < 2; i++) {                       // B: 1024 float4
            int idx = tid + i * 512;
            int r = idx >> 5, c = (idx & 31) * 4;
            cp_async16(&Bs[(s * GBK + r) * GBP + c],
                       &B[(size_t)(k0 + r) * N + bn + c]);
        }
    };

    const int KT = K / GBK;
    load_stage(0, 0);
    cp_commit();
    if (KT > 1) { load_stage(1, GBK); cp_commit(); }

    for (int kt = 0; kt < KT; kt++) {
        if (kt + 2 < KT) {
            load_stage((kt + 2) % GST, (kt + 2) * GBK);
            cp_commit();
            cp_wait<2>();
        } else if (kt + 1 < KT) {
            cp_wait<1>();
        } else {
            cp_wait<0>();
        }
        __syncthreads();

        const float* as = &As[(kt % GST) * GBM * GAP];
        const float* bs = &Bs[(kt % GST) * GBK * GBP];

        #pragma unroll
        for (int kk = 0; kk < GBK; kk += 8) {
            wmma::fragment<wmma::matrix_a, 16, 16, 8, wmma::precision::tf32, wmma::row_major> af[2];
            #pragma unroll
            for (int i = 0; i < 2; i++) {
                wmma::load_matrix_sync(af[i], &as[(wm * 32 + i * 16) * GAP + kk], GAP);
                #pragma unroll
                for (int e = 0; e < af[i].num_elements; e++)
                    af[i].x[e] = wmma::__float_to_tf32(af[i].x[e]);
            }
            #pragma unroll
            for (int j = 0; j < 2; j++) {
                wmma::fragment<wmma::matrix_b, 16, 16, 8, wmma::precision::tf32, wmma::row_major> bf;
                wmma::load_matrix_sync(bf, &bs[kk * GBP + wn * 32 + j * 16], GBP);
                #pragma unroll
                for (int e = 0; e < bf.num_elements; e++)
                    bf.x[e] = wmma::__float_to_tf32(bf.x[e]);
                #pragma unroll
                for (int i = 0; i < 2; i++)
                    wmma::mma_sync(acc[i][j], af[i], bf, acc[i][j]);
            }
        }
        __syncthreads();   // protects stage reuse: prefetch at kt+1 targets (kt+3)%3 == kt%3
    }

    #pragma unroll
    for (int i = 0; i < 2; i++)
        #pragma unroll
        for (int j = 0; j < 2; j++)
            wmma::store_matrix_sync(
                &C[(size_t)(bm + wm * 32 + i * 16) * N + bn + wn * 32 + j * 16],
                acc[i][j], N, wmma::mem_row_major);
}

#define GEMM_SMEM ((GST * GBM * GAP + GST * GBK * GBP) * sizeof(float))  // 105984

// ---------------------------------------------------------------------------
// Concatenate wk || wv into g_wkv  [2048 rows x 1024 cols]
// ---------------------------------------------------------------------------
__global__ void concat_wkv_kernel(const float* __restrict__ wk,
                                  const float* __restrict__ wv,
                                  float* __restrict__ wkv) {
    int idx = blockIdx.x * blockDim.x + threadIdx.x;   // float4 index
    if (idx >= PC * (PKV2 / 4)) return;
    int r  = idx >> 8;            // 0..2047
    int c4 = idx & 255;           // 0..255
    float4 val = (c4 < 128)
        ? reinterpret_cast<const float4*>(wk)[r * 128 + c4]
        : reinterpret_cast<const float4*>(wv)[r * 128 + (c4 - 128)];
    reinterpret_cast<float4*>(wkv)[idx] = val;
}

// ---------------------------------------------------------------------------
// RoPE tables (double precision, once per launch)
// ---------------------------------------------------------------------------
__global__ void rope_table_kernel() {
    int idx = blockIdx.x * blockDim.x + threadIdx.x;
    if (idx >= PT * 32) return;
    int t = idx >> 5, i = idx & 31;
    double freq = exp(-(double)i * (9.210340371976184 / 32.0)); // ln(10000)/32
    double s, c;
    sincos((double)t * freq, &s, &c);
    g_cos[idx] = (float)c;
    g_sin[idx] = (float)s;
}

// RoPE on q (contiguous [PM, PC])
__global__ void rope_apply_q_kernel(float* __restrict__ buf) {
    int idx = blockIdx.x * blockDim.x + threadIdx.x;   // pair index
    if (idx >= PM * (PC / 2)) return;
    int row = idx >> 10;                 // 1024 pairs per row
    int p   = idx & 1023;
    int i   = p & 31;
    int t   = row & (PT - 1);
    float c = g_cos[t * 32 + i], s = g_sin[t * 32 + i];
    float2 v = reinterpret_cast<float2*>(buf)[idx];
    float2 r;
    r.x = v.x * c - v.y * s;
    r.y = v.x * s + v.y * c;
    reinterpret_cast<float2*>(buf)[idx] = r;
}

// RoPE on k half of g_kv (rows PM, 8 heads x 64, row pitch 1024)
__global__ void rope_apply_k_kernel(float* __restrict__ buf) {
    int idx = blockIdx.x * blockDim.x + threadIdx.x;   // pair index
    if (idx >= PM * 256) return;
    int row  = idx >> 8;
    int p    = idx & 255;
    int i    = p & 31;
    int head = p >> 5;
    int t    = row & (PT - 1);
    float c = g_cos[t * 32 + i], s = g_sin[t * 32 + i];
    float* base = buf + (size_t)row * PKV2 + head * 64 + 2 * i;
    float2 v = *reinterpret_cast<float2*>(base);
    float2 r;
    r.x = v.x * c - v.y * s;
    r.y = v.x * s + v.y * c;
    *reinterpret_cast<float2*>(base) = r;
}

// ---------------------------------------------------------------------------
// Flash attention (non-causal, GQA rep=4) — EXACT R5 body (known-good perf),
// only the K/V base pointers changed to read the fused g_kv (pitch PKV2).
// One block = (b, h, 128-query tile). 256 thr = 8 warps, warp w owns rows
// [w*16, w*16+16). KV tiles of 64, cp.async double-buffered.
// smem floats: Qs 128*72 | Ks 2*64*72 | Vs 2*64*72 | Ss 128*72 | Ts 128*64
//              | Os 128*64 | mrow 128 | lrow 128 | crow 128 = 214,528 B
// ---------------------------------------------------------------------------
#define ALD 72

__global__ __launch_bounds__(256, 1)
void attn_kernel(const float* __restrict__ Q, const float* __restrict__ KV,
                 float* __restrict__ Out) {
    extern __shared__ float sm[];
    float* Qs   = sm;                   // 128*72
    float* Ks   = Qs  + 128 * ALD;      // 2 stages * 64*72
    float* Vs   = Ks  + 2 * 64 * ALD;   // 2 stages * 64*72
    float* Ss   = Vs  + 2 * 64 * ALD;   // 128*72
    float* Ts   = Ss  + 128 * ALD;      // 128*64
    float* Os   = Ts  + 128 * 64;       // 128*64
    float* mrow = Os  + 128 * 64;       // 128
    float* lrow = mrow + 128;           // 128
    float* crow = lrow + 128;           // 128

    const int tid  = threadIdx.x;
    const int warp = tid >> 5;
    const int qb = blockIdx.x, h = blockIdx.y, b = blockIdx.z;
    const int kh = h >> 2;                        // rep = 4
    const float scale = 0.125f;                   // 1/sqrt(64)

    const float* qg = Q  + ((size_t)(b * PT + qb * 128)) * PC + h * 64;
    const float* kg = KV + ((size_t)b * PT) * PKV2 + kh * 64;   // k half
    const float* vg = kg + PKV;                                 // v half

    // Load Q tile (128x64), zero O, init m/l.
    #pragma unroll
    for (int i = 0; i < 8; i++) {
        int idx = tid + i * 256;                  // 2048 float4 chunks
        int r = idx >> 4, c = (idx & 15) * 4;
        cp_async16(&Qs[r * ALD + c], &qg[(size_t)r * PC + c]);
    }
    #pragma unroll
    for (int i = 0; i < 8; i++)
        reinterpret_cast<float4*>(Os)[tid + i * 256] = make_float4(0.f, 0.f, 0.f, 0.f);
    if (tid < 128) { mrow[tid] = -1e30f; lrow[tid] = 0.f; }

    auto load_kv = [&](int s, int s0) {
        #pragma unroll
        for (int i = 0; i < 4; i++) {             // 1024 chunks per tensor
            int idx = tid + i * 256;
            int r = idx >> 4, c = (idx & 15) * 4;
            size_t g = (size_t)(s0 + r) * PKV2 + c;
            cp_async16(&Ks[(s * 64 + r) * ALD + c], &kg[g]);
            cp_async16(&Vs[(s * 64 + r) * ALD + c], &vg[g]);
        }
    };

    load_kv(0, 0);              // same commit group as Q
    cp_commit();

    const int NT = PT / 64;     // 32 KV tiles
    for (int it = 0; it < NT; it++) {
        if (it + 1 < NT) {
            load_kv((it + 1) & 1, (it + 1) * 64);
            cp_commit();
            cp_wait<1>();
        } else {
            cp_wait<0>();
        }
        __syncthreads();

        const float* ks = &Ks[(it & 1) * 64 * ALD];
        const float* vs = &Vs[(it & 1) * 64 * ALD];

        // S = Q @ K^T  (warp: 16 rows x 64 keys)
        {
            wmma::fragment<wmma::accumulator, 16, 16, 8, float> sacc[4];
            #pragma unroll
            for (int j = 0; j < 4; j++) wmma::fill_fragment(sacc[j], 0.f);
            #pragma unroll
            for (int kk = 0; kk < 64; kk += 8) {
                wmma::fragment<wmma::matrix_a, 16, 16, 8, wmma::precision::tf32, wmma::row_major> af;
                wmma::load_matrix_sync(af, &Qs[warp * 16 * ALD + kk], ALD);
                #pragma unroll
                for (int e = 0; e < af.num_elements; e++)
                    af.x[e] = wmma::__float_to_tf32(af.x[e]);
                #pragma unroll
                for (int j = 0; j < 4; j++) {
                    wmma::fragment<wmma::matrix_b, 16, 16, 8, wmma::precision::tf32, wmma::col_major> bf;
                    wmma::load_matrix_sync(bf, &ks[j * 16 * ALD + kk], ALD);
                    #pragma unroll
                    for (int e = 0; e < bf.num_elements; e++)
                        bf.x[e] = wmma::__float_to_tf32(bf.x[e]);
                    wmma::mma_sync(sacc[j], af, bf, sacc[j]);
                }
            }
            #pragma unroll
            for (int j = 0; j < 4; j++)
                wmma::store_matrix_sync(&Ss[warp * 16 * ALD + j * 16], sacc[j],
                                        ALD, wmma::mem_row_major);
        }
        __syncthreads();

        // Online softmax: 2 threads per row (tid and tid^1), 32 cols each.
        {
            int row  = tid >> 1;
            int half = tid & 1;
            float* srow = &Ss[row * ALD + half * 32];
            float m_old = mrow[row];
            float rm = -1e30f;
            #pragma unroll
            for (int c = 0; c < 32; c++) rm = fmaxf(rm, srow[c] * scale);
            rm = fmaxf(rm, __shfl_xor_sync(0xFFFFFFFFu, rm, 1));
            rm = fmaxf(rm, m_old);
            float sum = 0.f;
            #pragma unroll
            for (int c = 0; c < 32; c++) {
                float p = __expf(srow[c] * scale - rm);
                srow[c] = p;
                sum += p;
            }
            sum += __shfl_xor_sync(0xFFFFFFFFu, sum, 1);
            if (half == 0) {
                float corr = __expf(m_old - rm);
                mrow[row] = rm;
                lrow[row] = lrow[row] * corr + sum;
                crow[row] = corr;
            }
        }
        __syncthreads();

        // T = P @ V  (warp: 16 rows x 64 dims)
        {
            wmma::fragment<wmma::accumulator, 16, 16, 8, float> oacc[4];
            #pragma unroll
            for (int j = 0; j < 4; j++) wmma::fill_fragment(oacc[j], 0.f);
            #pragma unroll
            for (int kk = 0; kk < 64; kk += 8) {
                wmma::fragment<wmma::matrix_a, 16, 16, 8, wmma::precision::tf32, wmma::row_major> af;
                wmma::load_matrix_sync(af, &Ss[warp * 16 * ALD + kk], ALD);
                #pragma unroll
                for (int e = 0; e < af.num_elements; e++)
                    af.x[e] = wmma::__float_to_tf32(af.x[e]);
                #pragma unroll
                for (int j = 0; j < 4; j++) {
                    wmma::fragment<wmma::matrix_b, 16, 16, 8, wmma::precision::tf32, wmma::row_major> bf;
                    wmma::load_matrix_sync(bf, &vs[kk * ALD + j * 16], ALD);
                    #pragma unroll
                    for (int e = 0; e < bf.num_elements; e++)
                        bf.x[e] = wmma::__float_to_tf32(bf.x[e]);
                    wmma::mma_sync(oacc[j], af, bf, oacc[j]);
                }
            }
            #pragma unroll
            for (int j = 0; j < 4; j++)
                wmma::store_matrix_sync(&Ts[warp * 16 * 64 + j * 16], oacc[j],
                                        64, wmma::mem_row_major);
        }
        __syncthreads();

        // O = O * corr + T
        #pragma unroll
        for (int i = 0; i < 32; i++) {
            int idx = tid + i * 256;              // 0..8191
            int r = idx >> 6;
            Os[idx] = Os[idx] * crow[r] + Ts[idx];
        }
        __syncthreads();
    }

    // Write O / l
    float* og = Out + ((size_t)(b * PT + qb * 128)) * PC + h * 64;
    #pragma unroll
    for (int i = 0; i < 32; i++) {
        int idx = tid + i * 256;
        int r = idx >> 6, c = idx & 63;
        og[(size_t)r * PC + c] = Os[idx] / lrow[r];
    }
}

#define ATTN_SMEM_BYTES ((2 * 128 * ALD + 4 * 64 * ALD + 2 * 128 * 64 + 3 * 128) * sizeof(float))

// ---------------------------------------------------------------------------
// Launch
// ---------------------------------------------------------------------------
extern "C" void kernel_launch(void* const* d_in, const int* in_sizes, int n_in,
                              void* d_out, int out_size) {
    const float* x  = (const float*)d_in[0];
    const float* wq = (const float*)d_in[1];
    const float* wk = (const float*)d_in[2];
    const float* wv = (const float*)d_in[3];
    const float* wo = (const float*)d_in[4];
    float* out = (float*)d_out;

    float *q, *kv, *wkv, *a;
    cudaGetSymbolAddress((void**)&q,   g_q);
    cudaGetSymbolAddress((void**)&kv,  g_kv);
    cudaGetSymbolAddress((void**)&wkv, g_wkv);
    cudaGetSymbolAddress((void**)&a,   g_attn);

    cudaFuncSetAttribute(gemm_kernel,
                         cudaFuncAttributeMaxDynamicSharedMemorySize, (int)GEMM_SMEM);
    cudaFuncSetAttribute(attn_kernel,
                         cudaFuncAttributeMaxDynamicSharedMemorySize, (int)ATTN_SMEM_BYTES);

    // Tables + fused KV weight (cheap, deterministic)
    rope_table_kernel<<<(PT * 32 + 255) / 256, 256>>>();
    concat_wkv_kernel<<<(PC * (PKV2 / 4) + 255) / 256, 256>>>(wk, wv, wkv);

    // Projections
    gemm_kernel<<<dim3(PC / GBN,   PM / GBM), 512, GEMM_SMEM>>>(x, wq,  q,  PM, PC,   PC);
    gemm_kernel<<<dim3(PKV2 / GBN, PM / GBM), 512, GEMM_SMEM>>>(x, wkv, kv, PM, PKV2, PC);

    // RoPE on q and k
    rope_apply_q_kernel<<<(PM * (PC / 2) + 255) / 256, 256>>>(q);
    rope_apply_k_kernel<<<(PM * 256 + 255) / 256, 256>>>(kv);

    // Attention
    attn_kernel<<<dim3(PT / 128, PH, PB), 256, ATTN_SMEM_BYTES>>>(q, kv, a);

    // Output projection
    gemm_kernel<<<dim3(PC / GBN, PM / GBM), 512, GEMM_SMEM>>>(a, wo, out, PM, PC, PC);
}

// round 12
// speedup vs baseline: 1.4961x; 1.0328x over previous
#include <cuda_runtime.h>
#include <cuda_bf16.h>
#include <mma.h>
#include <math.h>

using namespace nvcuda;

// ---------------------------------------------------------------------------
// Problem constants
// ---------------------------------------------------------------------------
#define PB     2
#define PT     2048
#define PC     2048
#define PH     32
#define PKVH   8
#define PHD    64
#define PKV    (PKVH * PHD)      // 512
#define PKV2   (2 * PKV)         // 1024 (k||v fused)
#define PM     (PB * PT)         // 4096

// ---------------------------------------------------------------------------
// Device scratch (no cudaMalloc allowed)
// All MMA operands are pre-rounded to tf32 (low 13 mantissa bits zero), so
// the GEMM / attention inner loops carry NO per-element conversions.
// ---------------------------------------------------------------------------
__device__ float g_x[PM * PC];        // 32 MB  x, tf32-rounded
__device__ float g_wq[PC * PC];       // 16 MB  wq, tf32-rounded
__device__ float g_wo[PC * PC];       // 16 MB  wo, tf32-rounded
__device__ float g_wkv[PC * PKV2];    //  8 MB  wk||wv, tf32-rounded
__device__ float g_q[PM * PC];        // 32 MB  q (rounded by rope)
__device__ float g_kv[PM * PKV2];     // 16 MB  k||v (k rounded by rope, v by pass)
__device__ float g_attn[PM * PC];     // 32 MB  attn out (rounded at epilogue)
__device__ float g_cos[PT * 32];
__device__ float g_sin[PT * 32];

// ---------------------------------------------------------------------------
// cp.async helpers
// ---------------------------------------------------------------------------
__device__ __forceinline__ void cp_async16(void* s, const void* g) {
    unsigned sa = (unsigned)__cvta_generic_to_shared(s);
    asm volatile("cp.async.cg.shared.global [%0], [%1], 16;" :: "r"(sa), "l"(g));
}
__device__ __forceinline__ void cp_commit() {
    asm volatile("cp.async.commit_group;");
}
template<int N> __device__ __forceinline__ void cp_wait() {
    asm volatile("cp.async.wait_group %0;" :: "n"(N));
}

__device__ __forceinline__ float tf32r(float x) { return wmma::__float_to_tf32(x); }

// ---------------------------------------------------------------------------
// Rounded copy: dst = tf32_round(src), float4-vectorized.
// ---------------------------------------------------------------------------
__global__ void round_copy_kernel(float* __restrict__ dst,
                                  const float* __restrict__ src, int n4) {
    int idx = blockIdx.x * blockDim.x + threadIdx.x;
    if (idx >= n4) return;
    float4 v = reinterpret_cast<const float4*>(src)[idx];
    v.x = tf32r(v.x); v.y = tf32r(v.y); v.z = tf32r(v.z); v.w = tf32r(v.w);
    reinterpret_cast<float4*>(dst)[idx] = v;
}

// Round the v half of g_kv in place (rows PM, cols [512,1024) of pitch 1024).
__global__ void round_v_kernel(float* __restrict__ kv) {
    int idx = blockIdx.x * blockDim.x + threadIdx.x;   // float4 within v half
    if (idx >= PM * (PKV / 4)) return;
    int row = idx >> 7;                 // 128 float4 per v-row
    int c4  = idx & 127;
    float4* p = reinterpret_cast<float4*>(kv + (size_t)row * PKV2 + PKV) + c4;
    float4 v = *p;
    v.x = tf32r(v.x); v.y = tf32r(v.y); v.z = tf32r(v.z); v.w = tf32r(v.w);
    *p = v;
}

// ---------------------------------------------------------------------------
// TF32 GEMM: C[M,N] = A[M,K] @ B[K,N], row-major fp32, operands pre-rounded.
// Block 128x128, BK=32, 3-stage cp.async. 512 threads = 16 warps (4x4),
// warp tile 32x32. NO per-element conversions in the mainloop.
// ---------------------------------------------------------------------------
#define GBM 128
#define GBN 128
#define GBK 32
#define GAP 36     // A smem pitch
#define GBP 132    // B smem pitch
#define GST 3      // stages

__global__ __launch_bounds__(512)
void gemm_kernel(const float* __restrict__ A, const float* __restrict__ B,
                 float* __restrict__ C, int M, int N, int K) {
    extern __shared__ float smem[];
    float* As = smem;                       // GST * 128 * 36
    float* Bs = smem + GST * GBM * GAP;     // GST * 32 * 132

    const int tid  = threadIdx.x;
    const int warp = tid >> 5;
    const int wm   = warp >> 2;             // 0..3 (M dir)
    const int wn   = warp & 3;              // 0..3 (N dir)
    const int bm   = blockIdx.y * GBM;
    const int bn   = blockIdx.x * GBN;

    wmma::fragment<wmma::accumulator, 16, 16, 8, float> acc[2][2];
    #pragma unroll
    for (int i = 0; i < 2; i++)
        #pragma unroll
        for (int j = 0; j < 2; j++)
            wmma::fill_fragment(acc[i][j], 0.0f);

    auto load_stage = [&](int s, int k0) {
        #pragma unroll
        for (int i = 0; i < 2; i++) {                       // A: 1024 float4
            int idx = tid + i * 512;
            int r = idx >> 3, c = (idx & 7) * 4;
            cp_async16(&As[(s * GBM + r) * GAP + c],
                       &A[(size_t)(bm + r) * K + k0 + c]);
        }
        #pragma unroll
        for (int i = 0; i < 2; i++) {                       // B: 1024 float4
            int idx = tid + i * 512;
            int r = idx >> 5, c = (idx & 31) * 4;
            cp_async16(&Bs[(s * GBK + r) * GBP + c],
                       &B[(size_t)(k0 + r) * N + bn + c]);
        }
    };

    const int KT = K / GBK;
    load_stage(0, 0);
    cp_commit();
    if (KT > 1) { load_stage(1, GBK); cp_commit(); }

    for (int kt = 0; kt < KT; kt++) {
        if (kt + 2 < KT) {
            load_stage((kt + 2) % GST, (kt + 2) * GBK);
            cp_commit();
            cp_wait<2>();
        } else if (kt + 1 < KT) {
            cp_wait<1>();
        } else {
            cp_wait<0>();
        }
        __syncthreads();

        const float* as = &As[(kt % GST) * GBM * GAP];
        const float* bs = &Bs[(kt % GST) * GBK * GBP];

        #pragma unroll
        for (int kk = 0; kk < GBK; kk += 8) {
            wmma::fragment<wmma::matrix_a, 16, 16, 8, wmma::precision::tf32, wmma::row_major> af[2];
            #pragma unroll
            for (int i = 0; i < 2; i++)
                wmma::load_matrix_sync(af[i], &as[(wm * 32 + i * 16) * GAP + kk], GAP);
            #pragma unroll
            for (int j = 0; j < 2; j++) {
                wmma::fragment<wmma::matrix_b, 16, 16, 8, wmma::precision::tf32, wmma::row_major> bf;
                wmma::load_matrix_sync(bf, &bs[kk * GBP + wn * 32 + j * 16], GBP);
                #pragma unroll
                for (int i = 0; i < 2; i++)
                    wmma::mma_sync(acc[i][j], af[i], bf, acc[i][j]);
            }
        }
        __syncthreads();   // protects stage reuse: prefetch at kt+1 targets (kt+3)%3 == kt%3
    }

    #pragma unroll
    for (int i = 0; i < 2; i++)
        #pragma unroll
        for (int j = 0; j < 2; j++)
            wmma::store_matrix_sync(
                &C[(size_t)(bm + wm * 32 + i * 16) * N + bn + wn * 32 + j * 16],
                acc[i][j], N, wmma::mem_row_major);
}

#define GEMM_SMEM ((GST * GBM * GAP + GST * GBK * GBP) * sizeof(float))  // 105984

// ---------------------------------------------------------------------------
// Concatenate wk || wv into g_wkv, tf32-rounded.
// ---------------------------------------------------------------------------
__global__ void concat_wkv_kernel(const float* __restrict__ wk,
                                  const float* __restrict__ wv,
                                  float* __restrict__ wkv) {
    int idx = blockIdx.x * blockDim.x + threadIdx.x;   // float4 index
    if (idx >= PC * (PKV2 / 4)) return;
    int r  = idx >> 8;            // 0..2047
    int c4 = idx & 255;           // 0..255
    float4 v = (c4 < 128)
        ? reinterpret_cast<const float4*>(wk)[r * 128 + c4]
        : reinterpret_cast<const float4*>(wv)[r * 128 + (c4 - 128)];
    v.x = tf32r(v.x); v.y = tf32r(v.y); v.z = tf32r(v.z); v.w = tf32r(v.w);
    reinterpret_cast<float4*>(wkv)[idx] = v;
}

// ---------------------------------------------------------------------------
// RoPE tables (double precision, once per launch)
// ---------------------------------------------------------------------------
__global__ void rope_table_kernel() {
    int idx = blockIdx.x * blockDim.x + threadIdx.x;
    if (idx >= PT * 32) return;
    int t = idx >> 5, i = idx & 31;
    double freq = exp(-(double)i * (9.210340371976184 / 32.0)); // ln(10000)/32
    double s, c;
    sincos((double)t * freq, &s, &c);
    g_cos[idx] = (float)c;
    g_sin[idx] = (float)s;
}

// RoPE on q (contiguous [PM, PC]); output tf32-rounded.
__global__ void rope_apply_q_kernel(float* __restrict__ buf) {
    int idx = blockIdx.x * blockDim.x + threadIdx.x;   // pair index
    if (idx >= PM * (PC / 2)) return;
    int row = idx >> 10;                 // 1024 pairs per row
    int p   = idx & 1023;
    int i   = p & 31;
    int t   = row & (PT - 1);
    float c = g_cos[t * 32 + i], s = g_sin[t * 32 + i];
    float2 v = reinterpret_cast<float2*>(buf)[idx];
    float2 r;
    r.x = tf32r(v.x * c - v.y * s);
    r.y = tf32r(v.x * s + v.y * c);
    reinterpret_cast<float2*>(buf)[idx] = r;
}

// RoPE on k half of g_kv (rows PM, 8 heads x 64, row pitch 1024); rounded.
__global__ void rope_apply_k_kernel(float* __restrict__ buf) {
    int idx = blockIdx.x * blockDim.x + threadIdx.x;   // pair index
    if (idx >= PM * 256) return;
    int row  = idx >> 8;
    int p    = idx & 255;
    int i    = p & 31;
    int head = p >> 5;
    int t    = row & (PT - 1);
    float c = g_cos[t * 32 + i], s = g_sin[t * 32 + i];
    float* base = buf + (size_t)row * PKV2 + head * 64 + 2 * i;
    float2 v = *reinterpret_cast<float2*>(base);
    float2 r;
    r.x = tf32r(v.x * c - v.y * s);
    r.y = tf32r(v.x * s + v.y * c);
    *reinterpret_cast<float2*>(base) = r;
}

// ---------------------------------------------------------------------------
// Flash attention (non-causal, GQA rep=4) — R5 body, conversions removed
// (Q/K/V pre-rounded; P rounded at softmax store; output rounded at write).
// One block = (b, h, 128-query tile). 256 thr = 8 warps.
// ---------------------------------------------------------------------------
#define ALD 72

__global__ __launch_bounds__(256, 1)
void attn_kernel(const float* __restrict__ Q, const float* __restrict__ KV,
                 float* __restrict__ Out) {
    extern __shared__ float sm[];
    float* Qs   = sm;                   // 128*72
    float* Ks   = Qs  + 128 * ALD;      // 2 stages * 64*72
    float* Vs   = Ks  + 2 * 64 * ALD;   // 2 stages * 64*72
    float* Ss   = Vs  + 2 * 64 * ALD;   // 128*72
    float* Ts   = Ss  + 128 * ALD;      // 128*64
    float* Os   = Ts  + 128 * 64;       // 128*64
    float* mrow = Os  + 128 * 64;       // 128
    float* lrow = mrow + 128;           // 128
    float* crow = lrow + 128;           // 128

    const int tid  = threadIdx.x;
    const int warp = tid >> 5;
    const int qb = blockIdx.x, h = blockIdx.y, b = blockIdx.z;
    const int kh = h >> 2;                        // rep = 4
    const float scale = 0.125f;                   // 1/sqrt(64)

    const float* qg = Q  + ((size_t)(b * PT + qb * 128)) * PC + h * 64;
    const float* kg = KV + ((size_t)b * PT) * PKV2 + kh * 64;   // k half
    const float* vg = kg + PKV;                                 // v half

    #pragma unroll
    for (int i = 0; i < 8; i++) {
        int idx = tid + i * 256;                  // 2048 float4 chunks
        int r = idx >> 4, c = (idx & 15) * 4;
        cp_async16(&Qs[r * ALD + c], &qg[(size_t)r * PC + c]);
    }
    #pragma unroll
    for (int i = 0; i < 8; i++)
        reinterpret_cast<float4*>(Os)[tid + i * 256] = make_float4(0.f, 0.f, 0.f, 0.f);
    if (tid < 128) { mrow[tid] = -1e30f; lrow[tid] = 0.f; }

    auto load_kv = [&](int s, int s0) {
        #pragma unroll
        for (int i = 0; i < 4; i++) {             // 1024 chunks per tensor
            int idx = tid + i * 256;
            int r = idx >> 4, c = (idx & 15) * 4;
            size_t g = (size_t)(s0 + r) * PKV2 + c;
            cp_async16(&Ks[(s * 64 + r) * ALD + c], &kg[g]);
            cp_async16(&Vs[(s * 64 + r) * ALD + c], &vg[g]);
        }
    };

    load_kv(0, 0);
    cp_commit();

    const int NT = PT / 64;     // 32 KV tiles
    for (int it = 0; it < NT; it++) {
        if (it + 1 < NT) {
            load_kv((it + 1) & 1, (it + 1) * 64);
            cp_commit();
            cp_wait<1>();
        } else {
            cp_wait<0>();
        }
        __syncthreads();

        const float* ks = &Ks[(it & 1) * 64 * ALD];
        const float* vs = &Vs[(it & 1) * 64 * ALD];

        // S = Q @ K^T  (warp: 16 rows x 64 keys) — no conversions.
        {
            wmma::fragment<wmma::accumulator, 16, 16, 8, float> sacc[4];
            #pragma unroll
            for (int j = 0; j < 4; j++) wmma::fill_fragment(sacc[j], 0.f);
            #pragma unroll
            for (int kk = 0; kk < 64; kk += 8) {
                wmma::fragment<wmma::matrix_a, 16, 16, 8, wmma::precision::tf32, wmma::row_major> af;
                wmma::load_matrix_sync(af, &Qs[warp * 16 * ALD + kk], ALD);
                #pragma unroll
                for (int j = 0; j < 4; j++) {
                    wmma::fragment<wmma::matrix_b, 16, 16, 8, wmma::precision::tf32, wmma::col_major> bf;
                    wmma::load_matrix_sync(bf, &ks[j * 16 * ALD + kk], ALD);
                    wmma::mma_sync(sacc[j], af, bf, sacc[j]);
                }
            }
            #pragma unroll
            for (int j = 0; j < 4; j++)
                wmma::store_matrix_sync(&Ss[warp * 16 * ALD + j * 16], sacc[j],
                                        ALD, wmma::mem_row_major);
        }
        __syncthreads();

        // Online softmax: 2 threads per row; store tf32-rounded P, fp32 sum.
        {
            int row  = tid >> 1;
            int half = tid & 1;
            float* srow = &Ss[row * ALD + half * 32];
            float m_old = mrow[row];
            float rm = -1e30f;
            #pragma unroll
            for (int c = 0; c < 32; c++) rm = fmaxf(rm, srow[c] * scale);
            rm = fmaxf(rm, __shfl_xor_sync(0xFFFFFFFFu, rm, 1));
            rm = fmaxf(rm, m_old);
            float sum = 0.f;
            #pragma unroll
            for (int c = 0; c < 32; c++) {
                float p = __expf(srow[c] * scale - rm);
                srow[c] = tf32r(p);
                sum += p;
            }
            sum += __shfl_xor_sync(0xFFFFFFFFu, sum, 1);
            if (half == 0) {
                float corr = __expf(m_old - rm);
                mrow[row] = rm;
                lrow[row] = lrow[row] * corr + sum;
                crow[row] = corr;
            }
        }
        __syncthreads();

        // T = P @ V  — no conversions.
        {
            wmma::fragment<wmma::accumulator, 16, 16, 8, float> oacc[4];
            #pragma unroll
            for (int j = 0; j < 4; j++) wmma::fill_fragment(oacc[j], 0.f);
            #pragma unroll
            for (int kk = 0; kk < 64; kk += 8) {
                wmma::fragment<wmma::matrix_a, 16, 16, 8, wmma::precision::tf32, wmma::row_major> af;
                wmma::load_matrix_sync(af, &Ss[warp * 16 * ALD + kk], ALD);
                #pragma unroll
                for (int j = 0; j < 4; j++) {
                    wmma::fragment<wmma::matrix_b, 16, 16, 8, wmma::precision::tf32, wmma::row_major> bf;
                    wmma::load_matrix_sync(bf, &vs[kk * ALD + j * 16], ALD);
                    wmma::mma_sync(oacc[j], af, bf, oacc[j]);
                }
            }
            #pragma unroll
            for (int j = 0; j < 4; j++)
                wmma::store_matrix_sync(&Ts[warp * 16 * 64 + j * 16], oacc[j],
                                        64, wmma::mem_row_major);
        }
        __syncthreads();

        // O = O * corr + T
        #pragma unroll
        for (int i = 0; i < 32; i++) {
            int idx = tid + i * 256;              // 0..8191
            int r = idx >> 6;
            Os[idx] = Os[idx] * crow[r] + Ts[idx];
        }
        __syncthreads();
    }

    // Write O / l, tf32-rounded (feeds the wo GEMM as A).
    float* og = Out + ((size_t)(b * PT + qb * 128)) * PC + h * 64;
    #pragma unroll
    for (int i = 0; i < 32; i++) {
        int idx = tid + i * 256;
        int r = idx >> 6, c = idx & 63;
        og[(size_t)r * PC + c] = tf32r(Os[idx] / lrow[r]);
    }
}

#define ATTN_SMEM_BYTES ((2 * 128 * ALD + 4 * 64 * ALD + 2 * 128 * 64 + 3 * 128) * sizeof(float))

// ---------------------------------------------------------------------------
// Launch
// ---------------------------------------------------------------------------
extern "C" void kernel_launch(void* const* d_in, const int* in_sizes, int n_in,
                              void* d_out, int out_size) {
    const float* x  = (const float*)d_in[0];
    const float* wq = (const float*)d_in[1];
    const float* wk = (const float*)d_in[2];
    const float* wv = (const float*)d_in[3];
    const float* wo = (const float*)d_in[4];
    float* out = (float*)d_out;

    float *xr, *wqr, *wor, *wkv, *q, *kv, *a;
    cudaGetSymbolAddress((void**)&xr,  g_x);
    cudaGetSymbolAddress((void**)&wqr, g_wq);
    cudaGetSymbolAddress((void**)&wor, g_wo);
    cudaGetSymbolAddress((void**)&wkv, g_wkv);
    cudaGetSymbolAddress((void**)&q,   g_q);
    cudaGetSymbolAddress((void**)&kv,  g_kv);
    cudaGetSymbolAddress((void**)&a,   g_attn);

    cudaFuncSetAttribute(gemm_kernel,
                         cudaFuncAttributeMaxDynamicSharedMemorySize, (int)GEMM_SMEM);
    cudaFuncSetAttribute(attn_kernel,
                         cudaFuncAttributeMaxDynamicSharedMemorySize, (int)ATTN_SMEM_BYTES);

    // Pre-rounded operands + tables (memory-bound, ~35us total)
    rope_table_kernel<<<(PT * 32 + 255) / 256, 256>>>();
    round_copy_kernel<<<(PM * PC / 4 + 255) / 256, 256>>>(xr,  x,  PM * PC / 4);
    round_copy_kernel<<<(PC * PC / 4 + 255) / 256, 256>>>(wqr, wq, PC * PC / 4);
    round_copy_kernel<<<(PC * PC / 4 + 255) / 256, 256>>>(wor, wo, PC * PC / 4);
    concat_wkv_kernel<<<(PC * (PKV2 / 4) + 255) / 256, 256>>>(wk, wv, wkv);

    // Projections (all operands tf32-rounded)
    gemm_kernel<<<dim3(PC / GBN,   PM / GBM), 512, GEMM_SMEM>>>(xr, wqr, q,  PM, PC,   PC);
    gemm_kernel<<<dim3(PKV2 / GBN, PM / GBM), 512, GEMM_SMEM>>>(xr, wkv, kv, PM, PKV2, PC);

    // RoPE on q and k (rounds outputs); round v half
    rope_apply_q_kernel<<<(PM * (PC / 2) + 255) / 256, 256>>>(q);
    rope_apply_k_kernel<<<(PM * 256 + 255) / 256, 256>>>(kv);
    round_v_kernel<<<(PM * (PKV / 4) + 255) / 256, 256>>>(kv);

    // Attention
    attn_kernel<<<dim3(PT / 128, PH, PB), 256, ATTN_SMEM_BYTES>>>(q, kv, a);

    // Output projection (out stays full fp32 accumulation)
    gemm_kernel<<<dim3(PC / GBN, PM / GBM), 512, GEMM_SMEM>>>(a, wor, out, PM, PC, PC);
}